// round 17
// baseline (speedup 1.0000x reference)
#include <cuda_runtime.h>
#include <cuda_fp16.h>
#include <math.h>

#define BB 2
#define SS 2048
#define DD 1024
#define HH 16
#define DP 64
#define MM (BB * SS)   // 4096
#define NZ (BB * HH)   // 32

// Scratch (allocation-free rule: __device__ globals). All MMA operands fp16.
__device__ __half g_q[MM * DD];                 // qh
__device__ __half g_k[MM * DD];                 // kh
__device__ __half g_v[MM * DD];                 // vh
__device__ __half g_vt[NZ * DP * SS];           // vh transposed: [(z*DP+d)][s]
__device__ __half g_c[MM * DD];                 // ctx
__device__ __half g_iq[MM * DD];                // inputs, fp16
__device__ __half g_ik[MM * DD];
__device__ __half g_iv[MM * DD];
__device__ __half g_wtT[4 * DD * DD];           // weights, fp16, TRANSPOSED [n][k]

// ---------------------------------------------------------------------------
// Helpers
// ---------------------------------------------------------------------------
__device__ __forceinline__ unsigned h2u(float lo, float hi) {
    unsigned r;
    asm("cvt.rn.f16x2.f32 %0, %1, %2;" : "=r"(r) : "f"(hi), "f"(lo));
    return r;
}

__device__ __forceinline__ void mma16(float* c, const unsigned* a, const unsigned* b) {
    asm volatile(
        "mma.sync.aligned.m16n8k16.row.col.f32.f16.f16.f32 "
        "{%0,%1,%2,%3}, {%4,%5,%6,%7}, {%8,%9}, {%0,%1,%2,%3};"
        : "+f"(c[0]), "+f"(c[1]), "+f"(c[2]), "+f"(c[3])
        : "r"(a[0]), "r"(a[1]), "r"(a[2]), "r"(a[3]), "r"(b[0]), "r"(b[1]));
}

// fp16 A-fragment load for m16n8k16: caller passes address for
// row = m_base + (lane & 15), u32-col = ku + (lane>>4)*4.
__device__ __forceinline__ void ldm_a(unsigned* a, unsigned addr) {
    asm volatile("ldmatrix.sync.aligned.m8n8.x4.shared.b16 {%0,%1,%2,%3}, [%4];"
                 : "=r"(a[0]), "=r"(a[1]), "=r"(a[2]), "=r"(a[3]) : "r"(addr));
}

__device__ __forceinline__ unsigned smem_u32(const void* p) {
    unsigned r;
    asm("{ .reg .u64 t; cvta.to.shared.u64 t, %1; cvt.u32.u64 %0, t; }"
        : "=r"(r) : "l"(p));
    return r;
}

__device__ __forceinline__ void cpasync16(unsigned s, const void* g) {
    asm volatile("cp.async.cg.shared.global [%0], [%1], 16;" :: "r"(s), "l"(g));
}

// ---------------------------------------------------------------------------
// Input conversion: q/k/v f32 -> fp16
// ---------------------------------------------------------------------------
__global__ void cvt_x(const float* __restrict__ q, const float* __restrict__ k,
                      const float* __restrict__ v,
                      __half* __restrict__ iq, __half* __restrict__ ik,
                      __half* __restrict__ iv) {
    const int seg = blockIdx.y;
    const float* src = (seg == 0) ? q : (seg == 1) ? k : v;
    __half* dst = (seg == 0) ? iq : (seg == 1) ? ik : iv;
    int i = (blockIdx.x * 256 + threadIdx.x) * 4;
    float4 x = *(const float4*)(src + i);
    uint2 o;
    o.x = h2u(x.x, x.y);
    o.y = h2u(x.z, x.w);
    *(uint2*)(dst + i) = o;
}

// ---------------------------------------------------------------------------
// Weight convert + transpose: W[k][n] f32 -> wtT[n][k] fp16 (per weight z).
// ---------------------------------------------------------------------------
__global__ void cvt_w(const float* __restrict__ Wq, const float* __restrict__ Wk,
                      const float* __restrict__ Wv, const float* __restrict__ Wo,
                      __half* __restrict__ wtT) {
    __shared__ __half tile[32][33];
    const int w = blockIdx.z;
    const float* W = (w == 0) ? Wq : (w == 1) ? Wk : (w == 2) ? Wv : Wo;
    __half* dst = wtT + (size_t)w * DD * DD;
    const int k0 = blockIdx.y * 32, n0 = blockIdx.x * 32;
    const int tx = threadIdx.x, ty = threadIdx.y;   // (32, 8)
    #pragma unroll
    for (int j = 0; j < 4; j++) {
        int kk = ty + 8 * j;
        tile[kk][tx] = __float2half_rn(W[(size_t)(k0 + kk) * DD + n0 + tx]);
    }
    __syncthreads();
    #pragma unroll
    for (int j = 0; j < 4; j++) {
        int nn = ty + 8 * j;
        dst[(size_t)(n0 + nn) * DD + k0 + tx] = tile[tx][nn];
    }
}

// ---------------------------------------------------------------------------
// vh transpose: g_v [b*SS+s][DD] (head slice) -> g_vt [(z*DP+d)][s]
// ---------------------------------------------------------------------------
__global__ void transpose_v(const __half* __restrict__ vh, __half* __restrict__ vt) {
    __shared__ __half tile[32][33];
    const int z = blockIdx.z;
    const int b = z >> 4, h = z & 15;
    const int s0 = blockIdx.x * 32, d0 = blockIdx.y * 32;
    const int tx = threadIdx.x, ty = threadIdx.y;   // (32, 8)
    #pragma unroll
    for (int j = 0; j < 4; j++) {
        int ss = ty + 8 * j;
        tile[ss][tx] = vh[(size_t)(b * SS + s0 + ss) * DD + h * DP + d0 + tx];
    }
    __syncthreads();
    #pragma unroll
    for (int j = 0; j < 4; j++) {
        int dd = ty + 8 * j;
        vt[(size_t)(z * DP + d0 + dd) * SS + s0 + tx] = tile[tx][dd];
    }
}

// ---------------------------------------------------------------------------
// fp16 GEMM + bias: tile 128x128, K-tile 64, 2-stage, A-frags via ldmatrix.
// ---------------------------------------------------------------------------
#define G_STR 36
#define G_STG_U (2 * 128 * G_STR)     // 9216
#define GEMM_SMEM_BYTES (2 * G_STG_U * 4)   // 73728

__device__ __forceinline__ void gemm_load_tile(const __half* __restrict__ A,
                                               const __half* __restrict__ Bt,
                                               int Kdim, int m0, int n0, int k0,
                                               unsigned* stage) {
    const int tid = threadIdx.x;
    unsigned sA = smem_u32(stage);
    unsigned sB = smem_u32(stage + 128 * G_STR);
    #pragma unroll
    for (int i = tid; i < 1024; i += 256) {
        int r = i >> 3, c = i & 7;
        cpasync16(sA + (r * G_STR + c * 4) * 4, A + (size_t)(m0 + r) * Kdim + k0 + c * 8);
    }
    #pragma unroll
    for (int i = tid; i < 1024; i += 256) {
        int r = i >> 3, c = i & 7;
        cpasync16(sB + (r * G_STR + c * 4) * 4, Bt + (size_t)(n0 + r) * Kdim + k0 + c * 8);
    }
    asm volatile("cp.async.commit_group;");
}

template <bool OUT_HALF>
__device__ __forceinline__ void gemm_body(const __half* __restrict__ A,
                                          const __half* __restrict__ Bt,
                                          const float* __restrict__ bias,
                                          void* __restrict__ Cv,
                                          int Ndim, int Kdim,
                                          int m0, int n0,
                                          unsigned* smu) {
    const int tid = threadIdx.x;
    const int warp = tid >> 5, lane = tid & 31;
    const int g = lane >> 2, t = lane & 3;
    const int wm = warp >> 1, wn = warp & 1;
    const int lrow = lane & 15, kh4 = (lane >> 4) * 4;

    float acc[2][8][4] = {};

    gemm_load_tile(A, Bt, Kdim, m0, n0, 0, smu);

    int s = 0;
    for (int k0 = 0; k0 < Kdim; k0 += 64, s ^= 1) {
        if (k0 + 64 < Kdim) {
            gemm_load_tile(A, Bt, Kdim, m0, n0, k0 + 64, smu + (s ^ 1) * G_STG_U);
            asm volatile("cp.async.wait_group 1;");
        } else {
            asm volatile("cp.async.wait_group 0;");
        }
        __syncthreads();

        const unsigned* As = smu + s * G_STG_U;
        const unsigned* Bs = As + 128 * G_STR;

        #pragma unroll
        for (int ku = 0; ku < 32; ku += 8) {
            unsigned a[2][4], bfr[8][2];
            #pragma unroll
            for (int mt = 0; mt < 2; mt++)
                ldm_a(a[mt], smem_u32(As + (wm * 32 + mt * 16 + lrow) * G_STR + ku + kh4));
            #pragma unroll
            for (int nt = 0; nt < 8; nt++) {
                int n = wn * 64 + nt * 8 + g;
                bfr[nt][0] = Bs[n * G_STR + ku + t];
                bfr[nt][1] = Bs[n * G_STR + ku + t + 4];
            }
            #pragma unroll
            for (int mt = 0; mt < 2; mt++)
                #pragma unroll
                for (int nt = 0; nt < 8; nt++)
                    mma16(acc[mt][nt], a[mt], bfr[nt]);
        }
        __syncthreads();
    }

    #pragma unroll
    for (int mt = 0; mt < 2; mt++) {
        int row = m0 + wm * 32 + mt * 16 + g;
        #pragma unroll
        for (int nt = 0; nt < 8; nt++) {
            int col = n0 + wn * 64 + nt * 8 + 2 * t;
            float b0 = bias[col], b1 = bias[col + 1];
            float o00 = acc[mt][nt][0] + b0, o01 = acc[mt][nt][1] + b1;
            float o10 = acc[mt][nt][2] + b0, o11 = acc[mt][nt][3] + b1;
            if (OUT_HALF) {
                __half* C = (__half*)Cv;
                *(unsigned*)(C + (size_t)row * Ndim + col)       = h2u(o00, o01);
                *(unsigned*)(C + (size_t)(row + 8) * Ndim + col) = h2u(o10, o11);
            } else {
                float* C = (float*)Cv;
                C[(size_t)row * Ndim + col]           = o00;
                C[(size_t)row * Ndim + col + 1]       = o01;
                C[(size_t)(row + 8) * Ndim + col]     = o10;
                C[(size_t)(row + 8) * Ndim + col + 1] = o11;
            }
        }
    }
}

__global__ void __launch_bounds__(256, 2)
out_gemm(const __half* __restrict__ A, const __half* __restrict__ Bt,
         const float* __restrict__ bias, float* __restrict__ C) {
    extern __shared__ unsigned smu[];
    gemm_body<false>(A, Bt, bias, C, DD, DD, blockIdx.y * 128, blockIdx.x * 128, smu);
}

__global__ void __launch_bounds__(256, 2)
qkv_gemm(const __half* __restrict__ A0, const __half* __restrict__ A1,
         const __half* __restrict__ A2, const __half* __restrict__ Wt,
         const float* __restrict__ b0, const float* __restrict__ b1,
         const float* __restrict__ b2,
         __half* __restrict__ C0, __half* __restrict__ C1,
         __half* __restrict__ C2) {
    extern __shared__ unsigned smu[];
    const int z = blockIdx.z;
    const __half* A = (z == 0) ? A0 : (z == 1) ? A1 : A2;
    const __half* Bt = Wt + (size_t)z * DD * DD;
    const float* bs = (z == 0) ? b0 : (z == 1) ? b1 : b2;
    __half* C = (z == 0) ? C0 : (z == 1) ? C1 : C2;
    gemm_body<true>(A, Bt, bs, C, DD, DD, blockIdx.y * 128, blockIdx.x * 128, smu);
}

// ---------------------------------------------------------------------------
// Fused attention (round-16 proven, + ldmatrix A-frags).
// Phase 1: row sums of exp(S/8+mask) (no max). Phase 2: recompute S
// bit-identically, p=exp(.)*ri, streaming attn write, PV -> ctx.
// ---------------------------------------------------------------------------
#define QS_STR 36
#define K3_STR 36
#define V3_STR 36
#define P3F_STR 68
#define P3H_STR 36
#define AV3_STG_U (64 * K3_STR + 64 * V3_STR)   // 4608
#define AV3_Q_U   (128 * QS_STR)                // 4608
#define AV3_PF_U  (128 * P3F_STR)               // 8704
#define AV3_PH_U  (128 * P3H_STR)               // 4608
#define AV3_SMEM_BYTES ((AV3_Q_U + AV3_PF_U + AV3_PH_U + 2 * AV3_STG_U) * 4) // 108544

__device__ __forceinline__ void p1_load_k(const __half* __restrict__ K,
                                          int b, int h, int k0, unsigned* stage) {
    const int tid = threadIdx.x;
    unsigned sK = smem_u32(stage);
    #pragma unroll
    for (int i = tid; i < 1024; i += 256) {
        int r = i >> 3, c = i & 7;
        cpasync16(sK + (r * K3_STR + c * 4) * 4,
                  K + (size_t)(b * SS + k0 + r) * DD + h * DP + c * 8);
    }
    asm volatile("cp.async.commit_group;");
}

__device__ __forceinline__ void p2_load_tile(const __half* __restrict__ K,
                                             const __half* __restrict__ Vt,
                                             int b, int h, int z, int k0,
                                             unsigned* stage) {
    const int tid = threadIdx.x;
    unsigned sK = smem_u32(stage);
    unsigned sV = smem_u32(stage + 64 * K3_STR);
    #pragma unroll
    for (int i = tid; i < 512; i += 256) {
        int r = i >> 3, c = i & 7;
        cpasync16(sK + (r * K3_STR + c * 4) * 4,
                  K + (size_t)(b * SS + k0 + r) * DD + h * DP + c * 8);
    }
    #pragma unroll
    for (int i = tid; i < 512; i += 256) {
        int r = i >> 3, c = i & 7;
        cpasync16(sV + (r * V3_STR + c * 4) * 4,
                  Vt + (size_t)(z * DP + r) * SS + k0 + c * 8);
    }
    asm volatile("cp.async.commit_group;");
}

__global__ void __launch_bounds__(256, 2)
attn_fused(const __half* __restrict__ Q,
           const __half* __restrict__ K,
           const __half* __restrict__ Vt,
           const float* __restrict__ mask,
           float* __restrict__ attn,
           __half* __restrict__ C) {
    extern __shared__ unsigned smu[];
    unsigned* Qs = smu;                          // [128][36]
    float*    Pf = (float*)(smu + AV3_Q_U);      // [128][68] f32
    unsigned* Ps = smu + AV3_Q_U + AV3_PF_U;     // [128][36] fp16 units
    unsigned* stages = Ps + AV3_PH_U;            // 2 x AV3_STG_U
    __shared__ float psum[128 * 2];
    __shared__ float ri[128];

    const int z = blockIdx.y;
    const int b = z >> 4;
    const int h = z & 15;
    const int q0 = blockIdx.x * 128;
    const int tid = threadIdx.x;
    const int warp = tid >> 5, lane = tid & 31;
    const int g = lane >> 2, t = lane & 3;
    const int wm = warp >> 1, wn = warp & 1;
    const int lrow = lane & 15, kh4 = (lane >> 4) * 4;

    p1_load_k(K, b, h, 0, stages);

    // Q tile (resident all kernel)
    const uint4* Qb = (const uint4*)(Q + (size_t)(b * SS + q0) * DD + h * DP);
    const int row_u4 = DD / 8;
    #pragma unroll
    for (int i = tid; i < 128 * 8; i += 256) {
        int r = i >> 3, c = i & 7;
        uint4 vq = Qb[r * row_u4 + c];
        int cu = c * 4;
        Qs[r * QS_STR + cu + 0] = vq.x;
        Qs[r * QS_STR + cu + 1] = vq.y;
        Qs[r * QS_STR + cu + 2] = vq.z;
        Qs[r * QS_STR + cu + 3] = vq.w;
    }

    // =========================== Phase 1: row sums ===========================
    float sum_run[2][2] = {};
    for (int kt = 0; kt < SS / 128; kt++) {
        asm volatile("cp.async.wait_group 0;");
        __syncthreads();
        if (kt + 1 < SS / 128)
            p1_load_k(K, b, h, (kt + 1) * 128, stages + ((kt + 1) & 1) * AV3_STG_U);

        const unsigned* Ks = stages + (kt & 1) * AV3_STG_U;

        float acc[2][8][4] = {};
        #pragma unroll
        for (int du = 0; du < 32; du += 8) {
            unsigned a[2][4], bfr[8][2];
            #pragma unroll
            for (int mt = 0; mt < 2; mt++)
                ldm_a(a[mt], smem_u32(Qs + (wm * 32 + mt * 16 + lrow) * QS_STR + du + kh4));
            #pragma unroll
            for (int nt = 0; nt < 8; nt++) {
                int n = wn * 64 + nt * 8 + g;
                bfr[nt][0] = Ks[n * K3_STR + du + t];
                bfr[nt][1] = Ks[n * K3_STR + du + t + 4];
            }
            #pragma unroll
            for (int mt = 0; mt < 2; mt++)
                #pragma unroll
                for (int nt = 0; nt < 8; nt++)
                    mma16(acc[mt][nt], a[mt], bfr[nt]);
        }

        #pragma unroll
        for (int nt = 0; nt < 8; nt++) {
            int kj = kt * 128 + wn * 64 + nt * 8 + 2 * t;
            float mk0 = mask[b * SS + kj] * (-1e9f);
            float mk1 = mask[b * SS + kj + 1] * (-1e9f);
            #pragma unroll
            for (int mt = 0; mt < 2; mt++) {
                sum_run[mt][0] += __expf(acc[mt][nt][0] * 0.125f + mk0) +
                                  __expf(acc[mt][nt][1] * 0.125f + mk1);
                sum_run[mt][1] += __expf(acc[mt][nt][2] * 0.125f + mk0) +
                                  __expf(acc[mt][nt][3] * 0.125f + mk1);
            }
        }
        __syncthreads();
    }

    #pragma unroll
    for (int mt = 0; mt < 2; mt++)
        #pragma unroll
        for (int hi = 0; hi < 2; hi++) {
            float s = sum_run[mt][hi];
            s += __shfl_xor_sync(~0u, s, 1);
            s += __shfl_xor_sync(~0u, s, 2);
            if (t == 0) psum[(wm * 32 + mt * 16 + 8 * hi + g) * 2 + wn] = s;
        }
    __syncthreads();
    if (tid < 128) ri[tid] = 1.0f / (psum[tid * 2] + psum[tid * 2 + 1]);

    p2_load_tile(K, Vt, b, h, z, 0, stages);
    __syncthreads();

    // =========================== Phase 2: attn + PV ===========================
    float accC[2][4][4] = {};

    for (int it = 0; it < SS / 64; it++) {
        const int k0 = it * 64;
        asm volatile("cp.async.wait_group 0;");
        __syncthreads();

        if (it + 1 < SS / 64)
            p2_load_tile(K, Vt, b, h, z, k0 + 64, stages + ((it + 1) & 1) * AV3_STG_U);

        const unsigned* Ks = stages + (it & 1) * AV3_STG_U;
        const unsigned* Vs = Ks + 64 * K3_STR;

        #pragma unroll
        for (int half = 0; half < 2; half++) {
            float accS[2][2][4] = {};
            #pragma unroll
            for (int du = 0; du < 32; du += 8) {
                unsigned a[2][4], bfr[2][2];
                #pragma unroll
                for (int mt = 0; mt < 2; mt++)
                    ldm_a(a[mt], smem_u32(Qs + (wm * 32 + mt * 16 + lrow) * QS_STR + du + kh4));
                #pragma unroll
                for (int nt = 0; nt < 2; nt++) {
                    int n = half * 32 + wn * 16 + nt * 8 + g;
                    bfr[nt][0] = Ks[n * K3_STR + du + t];
                    bfr[nt][1] = Ks[n * K3_STR + du + t + 4];
                }
                #pragma unroll
                for (int mt = 0; mt < 2; mt++)
                    #pragma unroll
                    for (int nt = 0; nt < 2; nt++)
                        mma16(accS[mt][nt], a[mt], bfr[nt]);
            }

            #pragma unroll
            for (int nt = 0; nt < 2; nt++) {
                int kjl = half * 32 + wn * 16 + nt * 8 + 2 * t;
                int kj = k0 + kjl;
                float mk0 = mask[b * SS + kj] * (-1e9f);
                float mk1 = mask[b * SS + kj + 1] * (-1e9f);
                #pragma unroll
                for (int mt = 0; mt < 2; mt++) {
                    int row0 = wm * 32 + mt * 16 + g;
                    int row1 = row0 + 8;
                    float p00 = __expf(accS[mt][nt][0] * 0.125f + mk0) * ri[row0];
                    float p01 = __expf(accS[mt][nt][1] * 0.125f + mk1) * ri[row0];
                    float p10 = __expf(accS[mt][nt][2] * 0.125f + mk0) * ri[row1];
                    float p11 = __expf(accS[mt][nt][3] * 0.125f + mk1) * ri[row1];
                    Pf[row0 * P3F_STR + kjl]     = p00;
                    Pf[row0 * P3F_STR + kjl + 1] = p01;
                    Pf[row1 * P3F_STR + kjl]     = p10;
                    Pf[row1 * P3F_STR + kjl + 1] = p11;
                    Ps[row0 * P3H_STR + (kjl >> 1)] = h2u(p00, p01);
                    Ps[row1 * P3H_STR + (kjl >> 1)] = h2u(p10, p11);
                }
            }
        }
        __syncthreads();

        // coalesced streaming attn write
        #pragma unroll
        for (int i = tid; i < 2048; i += 256) {
            int r = i >> 4, c4 = (i & 15) * 4;
            float4 x = *(float4*)(Pf + r * P3F_STR + c4);
            __stcs((float4*)(attn + ((size_t)z * SS + q0 + r) * SS + k0 + c4), x);
        }

        // ctx += p @ V
        #pragma unroll
        for (int kku = 0; kku < 32; kku += 8) {
            unsigned a[2][4], bfr[4][2];
            #pragma unroll
            for (int mt = 0; mt < 2; mt++)
                ldm_a(a[mt], smem_u32(Ps + (wm * 32 + mt * 16 + lrow) * P3H_STR + kku + kh4));
            #pragma unroll
            for (int nt = 0; nt < 4; nt++) {
                int n = wn * 32 + nt * 8 + g;
                bfr[nt][0] = Vs[n * V3_STR + kku + t];
                bfr[nt][1] = Vs[n * V3_STR + kku + t + 4];
            }
            #pragma unroll
            for (int mt = 0; mt < 2; mt++)
                #pragma unroll
                for (int nt = 0; nt < 4; nt++)
                    mma16(accC[mt][nt], a[mt], bfr[nt]);
        }
    }

    // write ctx fp16 (consumed only by outproj MMA)
    #pragma unroll
    for (int mt = 0; mt < 2; mt++) {
        int qi = q0 + wm * 32 + mt * 16 + g;
        size_t base0 = (size_t)(b * SS + qi) * DD + h * DP;
        size_t base1 = base0 + (size_t)8 * DD;
        #pragma unroll
        for (int nt = 0; nt < 4; nt++) {
            int dj = wn * 32 + nt * 8 + 2 * t;
            *(unsigned*)(C + base0 + dj) = h2u(accC[mt][nt][0], accC[mt][nt][1]);
            *(unsigned*)(C + base1 + dj) = h2u(accC[mt][nt][2], accC[mt][nt][3]);
        }
    }
}

// ---------------------------------------------------------------------------
extern "C" void kernel_launch(void* const* d_in, const int* in_sizes, int n_in,
                              void* d_out, int out_size) {
    const float* q    = (const float*)d_in[0];
    const float* k    = (const float*)d_in[1];
    const float* v    = (const float*)d_in[2];
    const float* mask = (const float*)d_in[3];
    const float* Wq   = (const float*)d_in[4];
    const float* bq   = (const float*)d_in[5];
    const float* Wk   = (const float*)d_in[6];
    const float* bk   = (const float*)d_in[7];
    const float* Wv   = (const float*)d_in[8];
    const float* bv   = (const float*)d_in[9];
    const float* Wo   = (const float*)d_in[10];
    const float* bo   = (const float*)d_in[11];

    float* out  = (float*)d_out;
    float* attn = out + (size_t)MM * DD;   // output layout: (out, attn)

    __half *pq, *pk, *pv, *pvt, *pc, *piq, *pik, *piv, *pwtT;
    cudaGetSymbolAddress((void**)&pq, g_q);
    cudaGetSymbolAddress((void**)&pk, g_k);
    cudaGetSymbolAddress((void**)&pv, g_v);
    cudaGetSymbolAddress((void**)&pvt, g_vt);
    cudaGetSymbolAddress((void**)&pc, g_c);
    cudaGetSymbolAddress((void**)&piq, g_iq);
    cudaGetSymbolAddress((void**)&pik, g_ik);
    cudaGetSymbolAddress((void**)&piv, g_iv);
    cudaGetSymbolAddress((void**)&pwtT, g_wtT);

    cudaFuncSetAttribute(qkv_gemm, cudaFuncAttributeMaxDynamicSharedMemorySize,
                         GEMM_SMEM_BYTES);
    cudaFuncSetAttribute(out_gemm, cudaFuncAttributeMaxDynamicSharedMemorySize,
                         GEMM_SMEM_BYTES);
    cudaFuncSetAttribute(attn_fused, cudaFuncAttributeMaxDynamicSharedMemorySize,
                         AV3_SMEM_BYTES);

    dim3 gCvtX(MM * DD / (256 * 4), 3);             // (4096, 3)
    cvt_x<<<gCvtX, 256>>>(q, k, v, piq, pik, piv);

    dim3 gCvtW(DD / 32, DD / 32, 4);                // (32, 32, 4)
    cvt_w<<<gCvtW, dim3(32, 8)>>>(Wq, Wk, Wv, Wo, pwtT);

    dim3 gQKV(DD / 128, MM / 128, 3);               // (8, 32, 3)
    qkv_gemm<<<gQKV, 256, GEMM_SMEM_BYTES>>>(piq, pik, piv, pwtT,
                                             bq, bk, bv, pq, pk, pv);

    dim3 gTV(SS / 32, DP / 32, NZ);                 // (64, 2, 32)
    transpose_v<<<gTV, dim3(32, 8)>>>(pv, pvt);

    dim3 gAV(SS / 128, NZ);                         // (16, 32)
    attn_fused<<<gAV, 256, AV3_SMEM_BYTES>>>(pq, pk, pvt, mask, attn, pc);

    dim3 gProj(DD / 128, MM / 128);                 // (8, 32)
    out_gemm<<<gProj, 256, GEMM_SMEM_BYTES>>>(pc, pwtT + (size_t)3 * DD * DD,
                                              bo, out);
}